// round 16
// baseline (speedup 1.0000x reference)
#include <cuda_runtime.h>
#include <cuda_bf16.h>
#include <cstdint>

#define NROWS 65536
#define ZD    256
#define KCODES 1024
#define BM 128
#define NBLK (NROWS / BM)    // 512
#define TN 32                // codes per E tile
#define NT (KCODES / TN)     // 32 tiles
#define MARGIN 8e-3f
#define CAND_CAP 1280

#define ZQ_ELEMS ((size_t)NROWS * ZD)
#define IDX_OFF  ZQ_ELEMS
#define LOSS_OFF (ZQ_ELEMS + (size_t)NROWS)

#define ROWB 528                 // 264 bf16 padded row stride (bytes)
#define Z_SM (BM * ROWB)         // 67584
#define E_SM (TN * ROWB)         // 16896
#define SE_OFF(b) (Z_SM + (b) * E_SM)
#define DYN_SMEM (Z_SM + 2 * E_SM)   // 101376

typedef unsigned long long ull;

__device__ float g_enorm[KCODES];
__device__ float g_znorm[NROWS];
__device__ float g_partial[NBLK];
__device__ __nv_bfloat16 g_Ebf16[(size_t)KCODES * ZD];   // 512 KB, row-major

// ---------------- PTX helpers ----------------
__device__ __forceinline__ uint32_t smem_u32(const void* p) {
    uint32_t a;
    asm("{ .reg .u64 t; cvta.to.shared.u64 t, %1; cvt.u32.u64 %0, t; }" : "=r"(a) : "l"(p));
    return a;
}
__device__ __forceinline__ void cp_async16(uint32_t dst, const void* src) {
    asm volatile("cp.async.cg.shared.global [%0], [%1], 16;" :: "r"(dst), "l"(src) : "memory");
}
#define CP_COMMIT() asm volatile("cp.async.commit_group;" ::: "memory")
#define CP_WAIT(N)  asm volatile("cp.async.wait_group %0;" :: "n"(N) : "memory")

__device__ __forceinline__ void ldsm_x4(uint32_t& r0, uint32_t& r1, uint32_t& r2, uint32_t& r3,
                                        uint32_t addr) {
    asm volatile("ldmatrix.sync.aligned.m8n8.x4.shared.b16 {%0,%1,%2,%3}, [%4];"
                 : "=r"(r0), "=r"(r1), "=r"(r2), "=r"(r3) : "r"(addr));
}

// ================= K1: sum-of-squares per row, XLA row-reduce-tree bit-exact ==========
__global__ void sqsum_tree_kernel(const float* __restrict__ src, int nrows, int mode)
{
    int row = blockIdx.x * 8 + (threadIdx.x >> 5);
    if (row >= nrows) return;
    int lane = threadIdx.x & 31;
    const float2* p = (const float2*)(src + (size_t)row * ZD);
    float acc[4];
#pragma unroll
    for (int j = 0; j < 4; j++) {
        float2 v = p[lane + 32 * j];
        acc[j] = __fadd_rn(__fmul_rn(v.x, v.x), __fmul_rn(v.y, v.y));
    }
#pragma unroll
    for (int off = 16; off; off >>= 1)
#pragma unroll
        for (int j = 0; j < 4; j++)
            acc[j] = __fadd_rn(acc[j], __shfl_down_sync(0xffffffffu, acc[j], off));
    if (lane == 0) {
        float s = __fadd_rn(__fadd_rn(acc[0], acc[2]), __fadd_rn(acc[1], acc[3]));
        if (mode == 0) g_znorm[row] = s;
        else           g_enorm[row] = s;
    }
}

// ================= K1b: one-time E fp32 -> bf16 global conversion =================
__global__ void ecvt_kernel(const float* __restrict__ E)
{
    int idx = (blockIdx.x * 256 + threadIdx.x) * 4;
    float4 v = *(const float4*)(E + idx);
    __nv_bfloat162 b0 = __floats2bfloat162_rn(v.x, v.y);
    __nv_bfloat162 b1 = __floats2bfloat162_rn(v.z, v.w);
    uint2 pk;
    pk.x = *reinterpret_cast<unsigned*>(&b0);
    pk.y = *reinterpret_cast<unsigned*>(&b1);
    *(uint2*)(&g_Ebf16[idx]) = pk;
}

// ================= K2: HMMA candidate search + exact fp32 rescore =====================
// v16: BM=128 rows/CTA (halves chip-wide E re-ingestion: the LSU-op wall), TN=32 tiles,
// 2 CTA/SM. Warp = 32 rows x 16 codes (4 row-groups x 2 code-groups). A/B register
// double-buffered. Exact per-row prefix mins via sPairMin; overflow-safe fallback.
__global__ __launch_bounds__(256, 2) void vq_mma(
    const float* __restrict__ Z, const float* __restrict__ E, float* __restrict__ out)
{
    extern __shared__ __align__(16) char dyn[];
    __shared__ float sEn[KCODES];
    __shared__ unsigned sCand[CAND_CAP];
    __shared__ int sCnt;
    __shared__ int sOver;
    __shared__ ull sBest[BM];
    __shared__ float sRed[8];
    __shared__ float sPairMin[4][2][32];   // [mg][ng][row-in-32]

    const int tid = threadIdx.x;
    const int wid = tid >> 5, lane = tid & 31;
    const int g = lane >> 2, t = lane & 3;       // quad coords
    const int lr = lane & 7, ls = lane >> 3;     // ldmatrix coords
    const int mg = wid & 3;                      // row group: rows mg*32..+32
    const int ng = wid >> 2;                     // code group: codes ng*16..+16 in tile
    const int row0 = blockIdx.x * BM;

    const uint32_t smBase = smem_u32(dyn);
    const uint32_t smZ = smBase;

    for (int i = tid; i < KCODES; i += 256) sEn[i] = g_enorm[i];
    if (tid < BM) sBest[tid] = ~0ull;
    if (tid == 0) { sCnt = 0; sOver = 0; }

    // ---- Z tile: fp32 -> bf16 padded rows (128 x 256) ----
#pragma unroll
    for (int it = 0; it < 16; it++) {
        int lin = (tid + it * 256) * 8;
        int r = lin >> 8, k = lin & 255;
        float4 v0 = *(const float4*)(Z + (size_t)(row0 + r) * ZD + k);
        float4 v1 = *(const float4*)(Z + (size_t)(row0 + r) * ZD + k + 4);
        __nv_bfloat162 b0 = __floats2bfloat162_rn(v0.x, v0.y);
        __nv_bfloat162 b1 = __floats2bfloat162_rn(v0.z, v0.w);
        __nv_bfloat162 b2 = __floats2bfloat162_rn(v1.x, v1.y);
        __nv_bfloat162 b3 = __floats2bfloat162_rn(v1.z, v1.w);
        uint4 pk;
        pk.x = *reinterpret_cast<unsigned*>(&b0);
        pk.y = *reinterpret_cast<unsigned*>(&b1);
        pk.z = *reinterpret_cast<unsigned*>(&b2);
        pk.w = *reinterpret_cast<unsigned*>(&b3);
        *(uint4*)(dyn + r * ROWB + k * 2) = pk;
    }

    // ---- cp.async E tile 0 (32 rows x 512B = 1024 chunks) ----
#pragma unroll
    for (int i = 0; i < 4; i++) {
        int ch = tid + i * 256;
        int r = ch >> 5, c16 = ch & 31;
        cp_async16(smBase + SE_OFF(0) + r * ROWB + c16 * 16,
                   (const char*)g_Ebf16 + (size_t)r * 512 + c16 * 16);
    }
    CP_COMMIT();

    // ldmatrix base addresses (two m16 A frag sets; one x4 B load covers both n8 tiles)
    uint32_t aAddr[2];
#pragma unroll
    for (int m = 0; m < 2; m++)
        aAddr[m] = smZ + (uint32_t)((mg * 32 + m * 16 + (ls & 1) * 8 + lr) * ROWB + (ls >> 1) * 16);
    const uint32_t bOff = (uint32_t)((ng * 16 + (ls >> 1) * 8 + lr) * ROWB + (ls & 1) * 16);

    float runM[2][2];                     // [m][half] TRUE per-row prefix mins
    runM[0][0] = runM[0][1] = runM[1][0] = runM[1][1] = 3.402823466e38f;

    for (int ct = 0; ct < NT; ct++) {
        const int buf = ct & 1;
        if (ct < NT - 1) {
#pragma unroll
            for (int i = 0; i < 4; i++) {
                int ch = tid + i * 256;
                int r = ch >> 5, c16 = ch & 31;
                cp_async16(smBase + SE_OFF(buf ^ 1) + r * ROWB + c16 * 16,
                           (const char*)g_Ebf16 + (size_t)(ct + 1) * TN * 512
                                                + (size_t)r * 512 + c16 * 16);
            }
            CP_COMMIT();
            CP_WAIT(1);
        } else {
            CP_WAIT(0);
        }
        __syncthreads();

        const uint32_t smE = smBase + SE_OFF(buf);
        float dacc[2][2][4];              // [m16-group][n8-tile][frag]
#pragma unroll
        for (int m = 0; m < 2; m++)
#pragma unroll
            for (int nt = 0; nt < 2; nt++) {
                dacc[m][nt][0] = 0.f; dacc[m][nt][1] = 0.f;
                dacc[m][nt][2] = 0.f; dacc[m][nt][3] = 0.f;
            }

        // ---- register double-buffered mainloop ----
        uint32_t aq[2][2][4], bq[2][4];
        ldsm_x4(aq[0][0][0], aq[0][0][1], aq[0][0][2], aq[0][0][3], aAddr[0]);
        ldsm_x4(aq[0][1][0], aq[0][1][1], aq[0][1][2], aq[0][1][3], aAddr[1]);
        ldsm_x4(bq[0][0], bq[0][1], bq[0][2], bq[0][3], smE + bOff);
#pragma unroll
        for (int ks = 0; ks < 16; ks++) {
            const int cur = ks & 1, nxt = cur ^ 1;
            if (ks < 15) {
                ldsm_x4(aq[nxt][0][0], aq[nxt][0][1], aq[nxt][0][2], aq[nxt][0][3],
                        aAddr[0] + (ks + 1) * 32);
                ldsm_x4(aq[nxt][1][0], aq[nxt][1][1], aq[nxt][1][2], aq[nxt][1][3],
                        aAddr[1] + (ks + 1) * 32);
                ldsm_x4(bq[nxt][0], bq[nxt][1], bq[nxt][2], bq[nxt][3],
                        smE + bOff + (ks + 1) * 32);
            }
#pragma unroll
            for (int m = 0; m < 2; m++)
#pragma unroll
                for (int nt = 0; nt < 2; nt++) {
                    asm volatile(
                        "mma.sync.aligned.m16n8k16.row.col.f32.bf16.bf16.f32 "
                        "{%0,%1,%2,%3}, {%4,%5,%6,%7}, {%8,%9}, {%0,%1,%2,%3};"
                        : "+f"(dacc[m][nt][0]), "+f"(dacc[m][nt][1]),
                          "+f"(dacc[m][nt][2]), "+f"(dacc[m][nt][3])
                        : "r"(aq[cur][m][0]), "r"(aq[cur][m][1]),
                          "r"(aq[cur][m][2]), "r"(aq[cur][m][3]),
                          "r"(bq[cur][2 * nt]), "r"(bq[cur][2 * nt + 1]));
                }
        }

        // ---- scores + per-warp tile row-mins ----
        float v[2][2][4];
        float tmin[2][2];
        tmin[0][0] = tmin[0][1] = tmin[1][0] = tmin[1][1] = 3.402823466e38f;
#pragma unroll
        for (int m = 0; m < 2; m++)
#pragma unroll
            for (int nt = 0; nt < 2; nt++) {
                int c0 = ct * TN + ng * 16 + nt * 8 + 2 * t;
                float e0 = sEn[c0], e1 = sEn[c0 + 1];
                v[m][nt][0] = __fmaf_rn(-2.0f, dacc[m][nt][0], e0);
                v[m][nt][1] = __fmaf_rn(-2.0f, dacc[m][nt][1], e1);
                v[m][nt][2] = __fmaf_rn(-2.0f, dacc[m][nt][2], e0);
                v[m][nt][3] = __fmaf_rn(-2.0f, dacc[m][nt][3], e1);
                tmin[m][0] = fminf(tmin[m][0], fminf(v[m][nt][0], v[m][nt][1]));
                tmin[m][1] = fminf(tmin[m][1], fminf(v[m][nt][2], v[m][nt][3]));
            }
#pragma unroll
        for (int m = 0; m < 2; m++)
#pragma unroll
            for (int h = 0; h < 2; h++) {
                tmin[m][h] = fminf(tmin[m][h], __shfl_xor_sync(0xffffffffu, tmin[m][h], 1));
                tmin[m][h] = fminf(tmin[m][h], __shfl_xor_sync(0xffffffffu, tmin[m][h], 2));
            }
        if (t == 0) {
#pragma unroll
            for (int m = 0; m < 2; m++) {
                sPairMin[mg][ng][m * 16 + g]     = tmin[m][0];
                sPairMin[mg][ng][m * 16 + g + 8] = tmin[m][1];
            }
        }
        __syncthreads();                   // both ng halves visible
        float lim[2][2];
#pragma unroll
        for (int m = 0; m < 2; m++)
#pragma unroll
            for (int h = 0; h < 2; h++) {
                float c = fminf(sPairMin[mg][0][m * 16 + g + 8 * h],
                                sPairMin[mg][1][m * 16 + g + 8 * h]);
                runM[m][h] = fminf(runM[m][h], c);
                lim[m][h] = runM[m][h] + MARGIN;
            }
#pragma unroll
        for (int m = 0; m < 2; m++)
#pragma unroll
            for (int nt = 0; nt < 2; nt++) {
                int c0 = ct * TN + ng * 16 + nt * 8 + 2 * t;
                int rA = mg * 32 + m * 16 + g;
                int rB = rA + 8;
                if (v[m][nt][0] < lim[m][0]) {
                    int s = atomicAdd(&sCnt, 1);
                    if (s < CAND_CAP) sCand[s] = (unsigned)((rA << 10) | c0);
                }
                if (v[m][nt][1] < lim[m][0]) {
                    int s = atomicAdd(&sCnt, 1);
                    if (s < CAND_CAP) sCand[s] = (unsigned)((rA << 10) | (c0 + 1));
                }
                if (v[m][nt][2] < lim[m][1]) {
                    int s = atomicAdd(&sCnt, 1);
                    if (s < CAND_CAP) sCand[s] = (unsigned)((rB << 10) | c0);
                }
                if (v[m][nt][3] < lim[m][1]) {
                    int s = atomicAdd(&sCnt, 1);
                    if (s < CAND_CAP) sCand[s] = (unsigned)((rB << 10) | (c0 + 1));
                }
            }
        __syncthreads();                   // pushes + sPairMin reads done before reuse
    }

    // ================= exact fp32 rescore (reference op order) =================
    {
        int cnt = sCnt;
        if (cnt > CAND_CAP) {
            // overflow fallback (statistically unreachable): exhaustive per-row scan
            for (int rr = 0; rr < 16; rr++) {
                int i = wid * 16 + rr;
                int r = row0 + i;
                const float4* zp = (const float4*)(Z + (size_t)r * ZD);
                float zn = g_znorm[r];
                ull best = ~0ull;
                for (int c = lane; c < KCODES; c += 32) {
                    const float4* ep = (const float4*)(E + (size_t)c * ZD);
                    float acc = 0.0f;
#pragma unroll 8
                    for (int k = 0; k < 64; k++) {
                        float4 a = zp[k]; float4 b = ep[k];
                        acc = __fmaf_rn(a.x, b.x, acc);
                        acc = __fmaf_rn(a.y, b.y, acc);
                        acc = __fmaf_rn(a.z, b.z, acc);
                        acc = __fmaf_rn(a.w, b.w, acc);
                    }
                    float s = __fmaf_rn(-2.0f, acc, __fadd_rn(zn, sEn[c]));
                    ull key = ((ull)__float_as_uint(s) << 32) | (unsigned)c;
                    if (key < best) best = key;
                }
#pragma unroll
                for (int o = 16; o; o >>= 1) {
                    ull ob = __shfl_xor_sync(0xffffffffu, best, o);
                    if (ob < best) best = ob;
                }
                if (lane == 0) atomicMin(&sBest[i], best);
            }
        } else {
            for (int idx = tid; idx < cnt; idx += 256) {
                unsigned e = sCand[idx];
                int i = e >> 10;
                int c = e & 1023;
                int r = row0 + i;
                const float4* zp = (const float4*)(Z + (size_t)r * ZD);
                const float4* ep = (const float4*)(E + (size_t)c * ZD);
                float acc = 0.0f;     // serial k-ascending single-accumulator chain
#pragma unroll 8
                for (int k = 0; k < 64; k++) {
                    float4 a = zp[k];
                    float4 b = ep[k];
                    acc = __fmaf_rn(a.x, b.x, acc);
                    acc = __fmaf_rn(a.y, b.y, acc);
                    acc = __fmaf_rn(a.z, b.z, acc);
                    acc = __fmaf_rn(a.w, b.w, acc);
                }
                float s = __fmaf_rn(-2.0f, acc, __fadd_rn(g_znorm[r], sEn[c]));
                ull key = ((ull)__float_as_uint(s) << 32) | (unsigned)c;   // s > 0
                atomicMin(&sBest[i], key);   // min score, tie -> min index
            }
        }
    }
    __syncthreads();

    // ================= epilogue: gather z_q; z_q_st = fl(z + fl(z_q - z)); loss ========
    const float* Ablk = Z + (size_t)row0 * ZD;
    float lsum = 0.0f;
#pragma unroll
    for (int it = 0; it < 32; it++) {
        int e2 = tid + it * 256;
        int m = e2 >> 6;
        int c4 = (e2 & 63) * 4;
        int idx = (int)(unsigned)(sBest[m] & 0xffffffffull);
        float4 q  = *(const float4*)(E + (size_t)idx * ZD + c4);
        float4 z4 = *(const float4*)(Ablk + (size_t)m * ZD + c4);
        float d0 = __fadd_rn(q.x, -z4.x), d1 = __fadd_rn(q.y, -z4.y);
        float d2 = __fadd_rn(q.z, -z4.z), d3 = __fadd_rn(q.w, -z4.w);
        float4 o;
        o.x = __fadd_rn(z4.x, d0); o.y = __fadd_rn(z4.y, d1);
        o.z = __fadd_rn(z4.z, d2); o.w = __fadd_rn(z4.w, d3);
        lsum += d0 * d0 + d1 * d1 + d2 * d2 + d3 * d3;
        *(float4*)(out + (size_t)(row0 + m) * ZD + c4) = o;
    }
    if (tid < BM) out[IDX_OFF + row0 + tid] = (float)(unsigned)(sBest[tid] & 0xffffffffull);

#pragma unroll
    for (int o = 16; o; o >>= 1) lsum += __shfl_xor_sync(0xffffffffu, lsum, o);
    if ((tid & 31) == 0) sRed[tid >> 5] = lsum;
    __syncthreads();
    if (tid < 8) {
        float x = sRed[tid];
        x += __shfl_xor_sync(0xffu, x, 4);
        x += __shfl_xor_sync(0xffu, x, 2);
        x += __shfl_xor_sync(0xffu, x, 1);
        if (tid == 0) g_partial[blockIdx.x] = x;
    }
}

// ================= K3: deterministic final loss reduction (512 partials) ==============
__global__ void finalize_kernel(float* __restrict__ out) {
    __shared__ float s[16];
    int t = threadIdx.x;   // 512 threads
    float v = g_partial[t];
#pragma unroll
    for (int o = 16; o; o >>= 1) v += __shfl_xor_sync(0xffffffffu, v, o);
    if ((t & 31) == 0) s[t >> 5] = v;
    __syncthreads();
    if (t < 16) {
        float x = s[t];
        x += __shfl_xor_sync(0xffffu, x, 8);
        x += __shfl_xor_sync(0xffffu, x, 4);
        x += __shfl_xor_sync(0xffffu, x, 2);
        x += __shfl_xor_sync(0xffffu, x, 1);
        if (t == 0) {
            float mean = x / (float)((size_t)NROWS * ZD);
            out[LOSS_OFF] = mean + 0.25f * mean;   // (1 + BETA) * mean((z_q - z)^2)
        }
    }
}

extern "C" void kernel_launch(void* const* d_in, const int* in_sizes, int n_in,
                              void* d_out, int out_size) {
    const float* Z = (const float*)d_in[0];
    const float* E = (const float*)d_in[1];
    if (n_in >= 2 && in_sizes[0] < in_sizes[1]) { const float* t = Z; Z = E; E = t; }
    float* out = (float*)d_out;

    cudaFuncSetAttribute(vq_mma, cudaFuncAttributeMaxDynamicSharedMemorySize, DYN_SMEM);

    sqsum_tree_kernel<<<(NROWS + 7) / 8, 256>>>(Z, NROWS, 0);   // -> g_znorm
    sqsum_tree_kernel<<<(KCODES + 7) / 8, 256>>>(E, KCODES, 1); // -> g_enorm
    ecvt_kernel<<<KCODES * ZD / 1024, 256>>>(E);                // -> g_Ebf16
    vq_mma<<<NBLK, 256, DYN_SMEM>>>(Z, E, out);
    finalize_kernel<<<1, 512>>>(out);
}

// round 17
// speedup vs baseline: 52.5380x; 52.5380x over previous
#include <cuda_runtime.h>
#include <cuda_bf16.h>
#include <cuda_fp16.h>
#include <cstdint>

#define NROWS 65536
#define ZD    256
#define KCODES 1024
#define BM 128
#define NBLK (NROWS / BM)    // 512
#define MARGIN 8e-3f

#define ZQ_ELEMS ((size_t)NROWS * ZD)
#define IDX_OFF  ZQ_ELEMS
#define LOSS_OFF (ZQ_ELEMS + (size_t)NROWS)

#define ROWB 528                 // 264 bf16 padded row stride (bytes)
#define Z_SM (BM * ROWB)         // 67584
#define E_SM (BM * ROWB)         // 67584 (128-code tile)
#define SE_OFF(b) (Z_SM + (b) * E_SM)
#define DYN_SMEM (Z_SM + 2 * E_SM)   // 202752

typedef unsigned long long ull;

__device__ float  g_enorm[KCODES];
__device__ float  g_znorm[NROWS];
__device__ float  g_partial[NBLK];
__device__ __nv_bfloat16 g_Ebf16[(size_t)KCODES * ZD];     // 512 KB
__device__ __half2 g_srel[(size_t)NROWS * (KCODES / 2)];   // 128 MB scratch: -2*dot as f16

// ---------------- PTX helpers ----------------
__device__ __forceinline__ uint32_t smem_u32(const void* p) {
    uint32_t a;
    asm("{ .reg .u64 t; cvta.to.shared.u64 t, %1; cvt.u32.u64 %0, t; }" : "=r"(a) : "l"(p));
    return a;
}
__device__ __forceinline__ void cp_async16(uint32_t dst, const void* src) {
    asm volatile("cp.async.cg.shared.global [%0], [%1], 16;" :: "r"(dst), "l"(src) : "memory");
}
#define CP_COMMIT() asm volatile("cp.async.commit_group;" ::: "memory")
#define CP_WAIT(N)  asm volatile("cp.async.wait_group %0;" :: "n"(N) : "memory")

__device__ __forceinline__ void ldsm_x4(uint32_t& r0, uint32_t& r1, uint32_t& r2, uint32_t& r3,
                                        uint32_t addr) {
    asm volatile("ldmatrix.sync.aligned.m8n8.x4.shared.b16 {%0,%1,%2,%3}, [%4];"
                 : "=r"(r0), "=r"(r1), "=r"(r2), "=r"(r3) : "r"(addr));
}

// ================= K1: sum-of-squares per row, XLA row-reduce-tree bit-exact ==========
__global__ void sqsum_tree_kernel(const float* __restrict__ src, int nrows, int mode)
{
    int row = blockIdx.x * 8 + (threadIdx.x >> 5);
    if (row >= nrows) return;
    int lane = threadIdx.x & 31;
    const float2* p = (const float2*)(src + (size_t)row * ZD);
    float acc[4];
#pragma unroll
    for (int j = 0; j < 4; j++) {
        float2 v = p[lane + 32 * j];
        acc[j] = __fadd_rn(__fmul_rn(v.x, v.x), __fmul_rn(v.y, v.y));
    }
#pragma unroll
    for (int off = 16; off; off >>= 1)
#pragma unroll
        for (int j = 0; j < 4; j++)
            acc[j] = __fadd_rn(acc[j], __shfl_down_sync(0xffffffffu, acc[j], off));
    if (lane == 0) {
        float s = __fadd_rn(__fadd_rn(acc[0], acc[2]), __fadd_rn(acc[1], acc[3]));
        if (mode == 0) g_znorm[row] = s;
        else           g_enorm[row] = s;
    }
}

// ================= K1b: one-time E fp32 -> bf16 global conversion =================
__global__ void ecvt_kernel(const float* __restrict__ E)
{
    int idx = (blockIdx.x * 256 + threadIdx.x) * 4;
    float4 v = *(const float4*)(E + idx);
    __nv_bfloat162 b0 = __floats2bfloat162_rn(v.x, v.y);
    __nv_bfloat162 b1 = __floats2bfloat162_rn(v.z, v.w);
    uint2 pk;
    pk.x = *reinterpret_cast<unsigned*>(&b0);
    pk.y = *reinterpret_cast<unsigned*>(&b1);
    *(uint2*)(&g_Ebf16[idx]) = pk;
}

// ================= K2: round-8 two-phase architecture, upgraded feeds =================
// Phase 1: HMMA over all 8 E tiles (persistent A frags, ldmatrix B, cp.async E double
//          buffer); store -2*dot to g_srel (f16), track per-row FINAL min.
// Phase 2: scan g_srel vs finalMin+MARGIN -> tiny candidate list (~2/row).
// Phase 3: exact fp32 serial-k rescore; epilogue identical to round 8 (rel_err 0.0).
__global__ __launch_bounds__(256, 1) void vq_mma(
    const float* __restrict__ Z, const float* __restrict__ E, float* __restrict__ out)
{
    extern __shared__ __align__(16) char dyn[];
    __shared__ float sEn[KCODES];
    __shared__ float sMin[BM];
    __shared__ ull   sBest[BM];
    __shared__ unsigned sCand[8][512];
    __shared__ int   sCnt[8];
    __shared__ float sRed[8];

    const int tid = threadIdx.x;
    const int wid = tid >> 5, lane = tid & 31;
    const int g = lane >> 2, t = lane & 3;       // quad coords
    const int lr = lane & 7, ls = lane >> 3;     // ldmatrix coords
    const int row0 = blockIdx.x * BM;
    const int wr = wid * 16;                     // warp's 16-row slice

    const uint32_t smBase = smem_u32(dyn);
    const uint32_t smZ = smBase;

    for (int i = tid; i < KCODES; i += 256) sEn[i] = g_enorm[i];
    if (tid < BM) sBest[tid] = ~0ull;
    if (tid < 8)  sCnt[tid] = 0;

    // ---- Z tile: fp32 -> bf16 padded rows (128 x 256) ----
#pragma unroll
    for (int it = 0; it < 16; it++) {
        int lin = (tid + it * 256) * 8;
        int r = lin >> 8, k = lin & 255;
        float4 v0 = *(const float4*)(Z + (size_t)(row0 + r) * ZD + k);
        float4 v1 = *(const float4*)(Z + (size_t)(row0 + r) * ZD + k + 4);
        __nv_bfloat162 b0 = __floats2bfloat162_rn(v0.x, v0.y);
        __nv_bfloat162 b1 = __floats2bfloat162_rn(v0.z, v0.w);
        __nv_bfloat162 b2 = __floats2bfloat162_rn(v1.x, v1.y);
        __nv_bfloat162 b3 = __floats2bfloat162_rn(v1.z, v1.w);
        uint4 pk;
        pk.x = *reinterpret_cast<unsigned*>(&b0);
        pk.y = *reinterpret_cast<unsigned*>(&b1);
        pk.z = *reinterpret_cast<unsigned*>(&b2);
        pk.w = *reinterpret_cast<unsigned*>(&b3);
        *(uint4*)(dyn + r * ROWB + k * 2) = pk;
    }

    // ---- cp.async E tile 0 (128 rows x 512B = 4096 chunks) ----
#pragma unroll
    for (int i = 0; i < 16; i++) {
        int ch = tid + i * 256;
        int r = ch >> 5, c16 = ch & 31;
        cp_async16(smBase + SE_OFF(0) + r * ROWB + c16 * 16,
                   (const char*)g_Ebf16 + (size_t)r * 512 + c16 * 16);
    }
    CP_COMMIT();

    // ---- persistent A fragments: full K=256 for this warp's 16 rows (64 regs) ----
    __syncthreads();                       // Z stores visible to ldmatrix
    const uint32_t aAddr0 = smZ + (uint32_t)((wr + (ls & 1) * 8 + lr) * ROWB + (ls >> 1) * 16);
    uint32_t afr[16][4];
#pragma unroll
    for (int ks = 0; ks < 16; ks++)
        ldsm_x4(afr[ks][0], afr[ks][1], afr[ks][2], afr[ks][3], aAddr0 + ks * 32);

    const uint32_t bBase = (uint32_t)(((ls >> 1) * 8 + lr) * ROWB + (ls & 1) * 16);
    float minA = 3.402823466e38f, minB = 3.402823466e38f;

    // ================= phase 1: 8 E tiles of 128 codes =================
    for (int ct = 0; ct < 8; ct++) {
        const int buf = ct & 1;
        if (ct < 7) {
#pragma unroll
            for (int i = 0; i < 16; i++) {
                int ch = tid + i * 256;
                int r = ch >> 5, c16 = ch & 31;
                cp_async16(smBase + SE_OFF(buf ^ 1) + r * ROWB + c16 * 16,
                           (const char*)g_Ebf16 + (size_t)(ct + 1) * 128 * 512
                                                + (size_t)r * 512 + c16 * 16);
            }
            CP_COMMIT();
            CP_WAIT(1);
        } else {
            CP_WAIT(0);
        }
        __syncthreads();                   // tile ct resident; prev readers of buf done

        const uint32_t smE = smBase + SE_OFF(buf);
        float dacc[16][4];
#pragma unroll
        for (int nt = 0; nt < 16; nt++) {
            dacc[nt][0] = 0.f; dacc[nt][1] = 0.f; dacc[nt][2] = 0.f; dacc[nt][3] = 0.f;
        }
#pragma unroll
        for (int ks = 0; ks < 16; ks++) {
#pragma unroll
            for (int nb = 0; nb < 8; nb++) {      // one x4 covers two n8 tiles
                uint32_t b0, b1, b2, b3;
                ldsm_x4(b0, b1, b2, b3, smE + bBase + nb * (16 * ROWB) + ks * 32);
                asm volatile(
                    "mma.sync.aligned.m16n8k16.row.col.f32.bf16.bf16.f32 "
                    "{%0,%1,%2,%3}, {%4,%5,%6,%7}, {%8,%9}, {%0,%1,%2,%3};"
                    : "+f"(dacc[2 * nb][0]), "+f"(dacc[2 * nb][1]),
                      "+f"(dacc[2 * nb][2]), "+f"(dacc[2 * nb][3])
                    : "r"(afr[ks][0]), "r"(afr[ks][1]), "r"(afr[ks][2]), "r"(afr[ks][3]),
                      "r"(b0), "r"(b1));
                asm volatile(
                    "mma.sync.aligned.m16n8k16.row.col.f32.bf16.bf16.f32 "
                    "{%0,%1,%2,%3}, {%4,%5,%6,%7}, {%8,%9}, {%0,%1,%2,%3};"
                    : "+f"(dacc[2 * nb + 1][0]), "+f"(dacc[2 * nb + 1][1]),
                      "+f"(dacc[2 * nb + 1][2]), "+f"(dacc[2 * nb + 1][3])
                    : "r"(afr[ks][0]), "r"(afr[ks][1]), "r"(afr[ks][2]), "r"(afr[ks][3]),
                      "r"(b2), "r"(b3));
            }
        }

        // approx vals, running per-row mins, g_srel store (round-8 layout)
#pragma unroll
        for (int nt = 0; nt < 16; nt++) {
            int c = ct * 128 + nt * 8 + 2 * t;
            float e0 = sEn[c], e1 = sEn[c + 1];
            float m00 = -2.0f * dacc[nt][0], m01 = -2.0f * dacc[nt][1];
            float m10 = -2.0f * dacc[nt][2], m11 = -2.0f * dacc[nt][3];
            minA = fminf(minA, fminf(e0 + m00, e1 + m01));   // row wr+g
            minB = fminf(minB, fminf(e0 + m10, e1 + m11));   // row wr+g+8
            g_srel[(size_t)(row0 + wr + g) * 512 + (c >> 1)]     = __floats2half2_rn(m00, m01);
            g_srel[(size_t)(row0 + wr + g + 8) * 512 + (c >> 1)] = __floats2half2_rn(m10, m11);
        }
        __syncthreads();                   // all reads of buf done before next prefetch
    }

    // per-row FINAL min: reduce over the 4 t-lanes of each quad
    minA = fminf(minA, __shfl_xor_sync(0xffffffffu, minA, 1));
    minA = fminf(minA, __shfl_xor_sync(0xffffffffu, minA, 2));
    minB = fminf(minB, __shfl_xor_sync(0xffffffffu, minB, 1));
    minB = fminf(minB, __shfl_xor_sync(0xffffffffu, minB, 2));
    if (t == 0) { sMin[wr + g] = minA; sMin[wr + g + 8] = minB; }
    __syncthreads();

    // ================= phase 2: candidate scan (srel rows are L2-hot) =================
    for (int i = 0; i < 16; i++) {
        int rl = wr + i;
        float lim = sMin[rl] + MARGIN;
        const uint4* srow = (const uint4*)(g_srel + (size_t)(row0 + rl) * 512);
#pragma unroll
        for (int ch = 0; ch < 4; ch++) {
            uint4 u = srow[ch * 32 + lane];
            int cb = (ch * 32 + lane) * 8;
            unsigned w[4] = { u.x, u.y, u.z, u.w };
#pragma unroll
            for (int q = 0; q < 4; q++) {
                __half2 h = *reinterpret_cast<__half2*>(&w[q]);
                float2 f = __half22float2(h);
                int c0 = cb + 2 * q;
                if (sEn[c0] + f.x < lim) {
                    int slot = atomicAdd(&sCnt[wid], 1);
                    if (slot < 512) sCand[wid][slot] = (unsigned)((i << 10) | c0);
                }
                if (sEn[c0 + 1] + f.y < lim) {
                    int slot = atomicAdd(&sCnt[wid], 1);
                    if (slot < 512) sCand[wid][slot] = (unsigned)((i << 10) | (c0 + 1));
                }
            }
        }
    }
    __syncwarp();

    // ================= phase 3: exact fp32 rescore (reference op order) =================
    int cnt = sCnt[wid]; if (cnt > 512) cnt = 512;
    for (int base = 0; base < cnt; base += 32) {
        int idx = base + lane;
        if (idx < cnt) {
            unsigned e = sCand[wid][idx];
            int i = e >> 10, c = e & 1023;
            int r = row0 + wr + i;
            const float4* zp = (const float4*)(Z + (size_t)r * ZD);
            const float4* ep = (const float4*)(E + (size_t)c * ZD);
            float acc = 0.0f;            // serial k-ascending single-accumulator chain
#pragma unroll 8
            for (int k = 0; k < 64; k++) {
                float4 a = zp[k]; float4 b = ep[k];
                acc = __fmaf_rn(a.x, b.x, acc);
                acc = __fmaf_rn(a.y, b.y, acc);
                acc = __fmaf_rn(a.z, b.z, acc);
                acc = __fmaf_rn(a.w, b.w, acc);
            }
            float s = __fmaf_rn(-2.0f, acc, __fadd_rn(g_znorm[r], sEn[c]));
            ull key = ((ull)__float_as_uint(s) << 32) | (unsigned)c;  // s > 0 always
            atomicMin(&sBest[wr + i], key);    // min score, tie -> min index
        }
    }
    __syncthreads();

    // ================= epilogue: gather z_q; z_q_st = fl(z + fl(z_q - z)); loss ========
    const float* Ablk = Z + (size_t)row0 * ZD;
    float lsum = 0.0f;
    for (int e2 = tid; e2 < BM * (ZD / 4); e2 += 256) {
        int m = e2 >> 6;
        int c4 = (e2 & 63) * 4;
        int idx = (int)(unsigned)(sBest[m] & 0xffffffffull);
        float4 q  = *(const float4*)(E + (size_t)idx * ZD + c4);
        float4 z4 = *(const float4*)(Ablk + (size_t)m * ZD + c4);
        float d0 = __fadd_rn(q.x, -z4.x), d1 = __fadd_rn(q.y, -z4.y);
        float d2 = __fadd_rn(q.z, -z4.z), d3 = __fadd_rn(q.w, -z4.w);
        float4 o;
        o.x = __fadd_rn(z4.x, d0); o.y = __fadd_rn(z4.y, d1);
        o.z = __fadd_rn(z4.z, d2); o.w = __fadd_rn(z4.w, d3);
        lsum += d0 * d0 + d1 * d1 + d2 * d2 + d3 * d3;
        *(float4*)(out + (size_t)(row0 + m) * ZD + c4) = o;
    }
    if (tid < BM) out[IDX_OFF + row0 + tid] = (float)(unsigned)(sBest[tid] & 0xffffffffull);

#pragma unroll
    for (int o = 16; o; o >>= 1) lsum += __shfl_xor_sync(0xffffffffu, lsum, o);
    if ((tid & 31) == 0) sRed[tid >> 5] = lsum;
    __syncthreads();
    if (tid < 8) {
        float x = sRed[tid];
        x += __shfl_xor_sync(0xffu, x, 4);
        x += __shfl_xor_sync(0xffu, x, 2);
        x += __shfl_xor_sync(0xffu, x, 1);
        if (tid == 0) g_partial[blockIdx.x] = x;
    }
}

// ================= K3: deterministic final loss reduction =================
__global__ void finalize_kernel(float* __restrict__ out) {
    __shared__ float s[16];
    int t = threadIdx.x;   // 512 threads
    float v = g_partial[t];
#pragma unroll
    for (int o = 16; o; o >>= 1) v += __shfl_xor_sync(0xffffffffu, v, o);
    if ((t & 31) == 0) s[t >> 5] = v;
    __syncthreads();
    if (t < 16) {
        float x = s[t];
        x += __shfl_xor_sync(0xffffu, x, 8);
        x += __shfl_xor_sync(0xffffu, x, 4);
        x += __shfl_xor_sync(0xffffu, x, 2);
        x += __shfl_xor_sync(0xffffu, x, 1);
        if (t == 0) {
            float mean = x / (float)((size_t)NROWS * ZD);
            out[LOSS_OFF] = mean + 0.25f * mean;   // (1 + BETA) * mean((z_q - z)^2)
        }
    }
}

extern "C" void kernel_launch(void* const* d_in, const int* in_sizes, int n_in,
                              void* d_out, int out_size) {
    const float* Z = (const float*)d_in[0];
    const float* E = (const float*)d_in[1];
    if (n_in >= 2 && in_sizes[0] < in_sizes[1]) { const float* t = Z; Z = E; E = t; }
    float* out = (float*)d_out;

    cudaFuncSetAttribute(vq_mma, cudaFuncAttributeMaxDynamicSharedMemorySize, DYN_SMEM);

    sqsum_tree_kernel<<<(NROWS + 7) / 8, 256>>>(Z, NROWS, 0);   // -> g_znorm
    sqsum_tree_kernel<<<(KCODES + 7) / 8, 256>>>(E, KCODES, 1); // -> g_enorm
    ecvt_kernel<<<KCODES * ZD / 1024, 256>>>(E);                // -> g_Ebf16
    vq_mma<<<NBLK, 256, DYN_SMEM>>>(Z, E, out);
    finalize_kernel<<<1, 512>>>(out);
}